// round 1
// baseline (speedup 1.0000x reference)
#include <cuda_runtime.h>

// AbstractionLayer: B=524288, I=12, R=6, J=2, L=2, V=4
// out[b,r,l] = sum_{j,l'} M[r,l,j,l'] * softmax_sel[b,r,j,l'] + c[r,l]
// where M = head_W (contract V) body_W, c = head_W·sum_j body_b + head_b.
// Logits (softmax over i) reduced to coef[rj]·(f0,f1,f0^2,f1^2) since the
// template-only quadratic term is constant over the softmax axis.

#define NI 12   // input props
#define NR 6
#define NJ 2
#define NL 2
#define NV 4
#define NRJ 12  // R*J

__global__ __launch_bounds__(256, 4)
void abstraction_layer_kernel(
    const float* __restrict__ feat,       // [B, I, L]
    const float* __restrict__ templates,  // [R, J, L]
    const float* __restrict__ gammas,     // [R, J, L]
    const float* __restrict__ body_W,     // [R, J, V, L]
    const float* __restrict__ body_b,     // [R, J, V]
    const float* __restrict__ head_W,     // [R, L, V]
    const float* __restrict__ head_b,     // [R, L]
    float* __restrict__ out,              // [B, R, L]
    int B)
{
    __shared__ float s_coef[NRJ][4];  // per (r,j): [2*w*t0, 2*w*t1, -w0, -w1]
    __shared__ float s_M[NRJ][4];     // per (r,j): M[r,l,j,l'] at slot l*2+l'
    __shared__ float s_c[NR * NL];    // per (r,l)

    const int tid = threadIdx.x;

    // ---- one-time per-block parameter fusion (disjoint thread ranges) ----
    if (tid < NRJ) {
        const int r = tid >> 1, j = tid & 1;
        #pragma unroll
        for (int l = 0; l < NL; l++) {
            float g = gammas[(r * NJ + j) * NL + l];
            g = fminf(fmaxf(g, 0.0f), 1.0f);
            const float w = 1.0f - g;
            const float t = templates[(r * NJ + j) * NL + l];
            s_coef[tid][l]     = 2.0f * w * t;   // linear term
            s_coef[tid][2 + l] = -w;             // quadratic term
        }
    } else if (tid >= 16 && tid < 16 + 48) {
        // M[r,l,j,l2] = sum_v head_W[r,l,v] * body_W[r,j,v,l2]
        const int idx = tid - 16;
        const int l2 = idx & 1, j = (idx >> 1) & 1, l = (idx >> 2) & 1, r = idx >> 3;
        float acc = 0.0f;
        #pragma unroll
        for (int v = 0; v < NV; v++)
            acc += head_W[(r * NL + l) * NV + v] *
                   body_W[((r * NJ + j) * NV + v) * NL + l2];
        s_M[r * NJ + j][l * 2 + l2] = acc;
    } else if (tid >= 64 && tid < 64 + NR * NL) {
        // c[r,l] = sum_v head_W[r,l,v]*(body_b[r,0,v]+body_b[r,1,v]) + head_b[r,l]
        const int idx = tid - 64;
        const int r = idx >> 1, l = idx & 1;
        float acc = head_b[r * NL + l];
        #pragma unroll
        for (int v = 0; v < NV; v++)
            acc += head_W[(r * NL + l) * NV + v] *
                   (body_b[(r * NJ + 0) * NV + v] + body_b[(r * NJ + 1) * NV + v]);
        s_c[idx] = acc;
    }
    __syncthreads();

    const int b = blockIdx.x * blockDim.x + tid;
    if (b >= B) return;

    // ---- load 12x2 feature rows (24 floats, 16B-aligned: b*96 bytes) ----
    float f0[NI], f1[NI], q0[NI], q1[NI];
    const float4* fp = reinterpret_cast<const float4*>(feat + (size_t)b * (NI * NL));
    #pragma unroll
    for (int k = 0; k < 6; k++) {
        const float4 v4 = fp[k];
        f0[2 * k]     = v4.x; f1[2 * k]     = v4.y;
        f0[2 * k + 1] = v4.z; f1[2 * k + 1] = v4.w;
    }
    #pragma unroll
    for (int i = 0; i < NI; i++) { q0[i] = f0[i] * f0[i]; q1[i] = f1[i] * f1[i]; }

    float acc[NR * NL];
    #pragma unroll
    for (int k = 0; k < NR * NL; k++) acc[k] = s_c[k];

    // ---- 12 independent softmax-attention selections ----
    #pragma unroll
    for (int rj = 0; rj < NRJ; rj++) {
        const float c0 = s_coef[rj][0], c1 = s_coef[rj][1];
        const float c2 = s_coef[rj][2], c3 = s_coef[rj][3];

        float lg[NI];
        float m = -1e30f;
        #pragma unroll
        for (int i = 0; i < NI; i++) {
            float t = fmaf(c0, f0[i], fmaf(c1, f1[i], fmaf(c2, q0[i], c3 * q1[i])));
            lg[i] = t;
            m = fmaxf(m, t);
        }

        float se = 0.0f, n0 = 0.0f, n1 = 0.0f;
        #pragma unroll
        for (int i = 0; i < NI; i++) {
            const float e = __expf(lg[i] - m);
            se += e;
            n0 = fmaf(e, f0[i], n0);
            n1 = fmaf(e, f1[i], n1);
        }

        const float rinv = __frcp_rn(se);
        const float s0 = n0 * rinv, s1 = n1 * rinv;

        const int r = rj >> 1;
        acc[r * 2 + 0] = fmaf(s_M[rj][0], s0, fmaf(s_M[rj][1], s1, acc[r * 2 + 0]));
        acc[r * 2 + 1] = fmaf(s_M[rj][2], s0, fmaf(s_M[rj][3], s1, acc[r * 2 + 1]));
    }

    // ---- store 12 floats (b*48 bytes, 16B aligned) ----
    float4* op = reinterpret_cast<float4*>(out + (size_t)b * (NR * NL));
    op[0] = make_float4(acc[0], acc[1], acc[2],  acc[3]);
    op[1] = make_float4(acc[4], acc[5], acc[6],  acc[7]);
    op[2] = make_float4(acc[8], acc[9], acc[10], acc[11]);
}

extern "C" void kernel_launch(void* const* d_in, const int* in_sizes, int n_in,
                              void* d_out, int out_size) {
    const float* feat      = (const float*)d_in[0];
    const float* templates = (const float*)d_in[1];
    const float* gammas    = (const float*)d_in[2];
    const float* body_W    = (const float*)d_in[3];
    const float* body_b    = (const float*)d_in[4];
    const float* head_W    = (const float*)d_in[5];
    const float* head_b    = (const float*)d_in[6];
    float* out = (float*)d_out;

    const int B = in_sizes[0] / (NI * NL);
    const int threads = 256;
    const int blocks = (B + threads - 1) / threads;
    abstraction_layer_kernel<<<blocks, threads>>>(
        feat, templates, gammas, body_W, body_b, head_W, head_b, out, B);
}

// round 2
// speedup vs baseline: 1.1558x; 1.1558x over previous
#include <cuda_runtime.h>

// AbstractionLayer: B=524288, I=12, R=6, J=2, L=2, V=4
// Packed-f32x2 version: each thread processes elements (t, t+B/2).
// Softmax max-pass removed (logits provably in [-1.2, 2.4]); log2(e) folded
// into coefficients so exp == one raw ex2.approx. Head*body pre-fused to M.

#define NI 12
#define NR 6
#define NJ 2
#define NL 2
#define NV 4
#define NRJ 12
#define LOG2E 1.4426950408889634f

typedef unsigned long long u64;

__device__ __forceinline__ u64 pk2(float lo, float hi) {
    u64 r; asm("mov.b64 %0, {%1,%2};" : "=l"(r) : "f"(lo), "f"(hi)); return r;
}
__device__ __forceinline__ void upk2(u64 v, float& lo, float& hi) {
    asm("mov.b64 {%0,%1}, %2;" : "=f"(lo), "=f"(hi) : "l"(v));
}
__device__ __forceinline__ u64 fma2(u64 a, u64 b, u64 c) {
    u64 d; asm("fma.rn.f32x2 %0, %1, %2, %3;" : "=l"(d) : "l"(a), "l"(b), "l"(c)); return d;
}
__device__ __forceinline__ u64 mul2(u64 a, u64 b) {
    u64 d; asm("mul.rn.f32x2 %0, %1, %2;" : "=l"(d) : "l"(a), "l"(b)); return d;
}
__device__ __forceinline__ u64 add2(u64 a, u64 b) {
    u64 d; asm("add.rn.f32x2 %0, %1, %2;" : "=l"(d) : "l"(a), "l"(b)); return d;
}
__device__ __forceinline__ float ex2a(float x) {
    float r; asm("ex2.approx.ftz.f32 %0, %1;" : "=f"(r) : "f"(x)); return r;
}
__device__ __forceinline__ float rcpa(float x) {
    float r; asm("rcp.approx.ftz.f32 %0, %1;" : "=f"(r) : "f"(x)); return r;
}

__global__ __launch_bounds__(256, 2)
void abstraction_layer_kernel(
    const float* __restrict__ feat,       // [B, I, L]
    const float* __restrict__ templates,  // [R, J, L]
    const float* __restrict__ gammas,     // [R, J, L]
    const float* __restrict__ body_W,     // [R, J, V, L]
    const float* __restrict__ body_b,     // [R, J, V]
    const float* __restrict__ head_W,     // [R, L, V]
    const float* __restrict__ head_b,     // [R, L]
    float* __restrict__ out,              // [B, R, L]
    int B)
{
    __shared__ u64 s_coef[NRJ][4];  // duplicated-lane packed, scaled by log2e
    __shared__ u64 s_M[NRJ][4];     // duplicated-lane packed fused head*body
    __shared__ u64 s_c[NR * NL];    // duplicated-lane packed fused bias

    const int tid = threadIdx.x;

    // ---- one-time per-block parameter fusion (disjoint thread ranges) ----
    if (tid < NRJ) {
        const int r = tid >> 1, j = tid & 1;
        #pragma unroll
        for (int l = 0; l < NL; l++) {
            float g = gammas[(r * NJ + j) * NL + l];
            g = fminf(fmaxf(g, 0.0f), 1.0f);
            const float w = 1.0f - g;
            const float t = templates[(r * NJ + j) * NL + l];
            const float clin  = 2.0f * w * t * LOG2E;   // linear term (log2 domain)
            const float cquad = -w * LOG2E;             // quadratic term
            s_coef[tid][l]     = pk2(clin, clin);
            s_coef[tid][2 + l] = pk2(cquad, cquad);
        }
    } else if (tid >= 16 && tid < 16 + 48) {
        // M[r,l,j,l2] = sum_v head_W[r,l,v] * body_W[r,j,v,l2]
        const int idx = tid - 16;
        const int l2 = idx & 1, j = (idx >> 1) & 1, l = (idx >> 2) & 1, r = idx >> 3;
        float acc = 0.0f;
        #pragma unroll
        for (int v = 0; v < NV; v++)
            acc += head_W[(r * NL + l) * NV + v] *
                   body_W[((r * NJ + j) * NV + v) * NL + l2];
        s_M[r * NJ + j][l * 2 + l2] = pk2(acc, acc);
    } else if (tid >= 64 && tid < 64 + NR * NL) {
        // c[r,l] = sum_v head_W[r,l,v]*(body_b[r,0,v]+body_b[r,1,v]) + head_b[r,l]
        const int idx = tid - 64;
        const int r = idx >> 1, l = idx & 1;
        float acc = head_b[r * NL + l];
        #pragma unroll
        for (int v = 0; v < NV; v++)
            acc += head_W[(r * NL + l) * NV + v] *
                   (body_b[(r * NJ + 0) * NV + v] + body_b[(r * NJ + 1) * NV + v]);
        s_c[idx] = pk2(acc, acc);
    }
    __syncthreads();

    const int half = B >> 1;
    const int t = blockIdx.x * blockDim.x + tid;
    if (t >= half) return;

    // ---- load features of elements t and t+half, lane-pack them ----
    u64 F0[NI], F1[NI];
    const float4* fa = reinterpret_cast<const float4*>(feat + (size_t)t * (NI * NL));
    const float4* fb = reinterpret_cast<const float4*>(feat + (size_t)(t + half) * (NI * NL));
    #pragma unroll
    for (int k = 0; k < 6; k++) {
        const float4 a = fa[k];
        const float4 b = fb[k];
        F0[2 * k]     = pk2(a.x, b.x); F1[2 * k]     = pk2(a.y, b.y);
        F0[2 * k + 1] = pk2(a.z, b.z); F1[2 * k + 1] = pk2(a.w, b.w);
    }

    u64 acc[NR * NL];
    #pragma unroll
    for (int k = 0; k < NR * NL; k++) acc[k] = s_c[k];

    const u64 TWO  = 0x4000000040000000ULL;   // {2.0f, 2.0f}
    const u64 NEG1 = 0xBF800000BF800000ULL;   // {-1.0f, -1.0f}

    // ---- 12 independent softmax-attention selections (2 elems/thread) ----
    #pragma unroll
    for (int rj = 0; rj < NRJ; rj++) {
        const u64 c0 = s_coef[rj][0], c1 = s_coef[rj][1];
        const u64 c2 = s_coef[rj][2], c3 = s_coef[rj][3];

        u64 se = 0ULL, n0 = 0ULL, n1 = 0ULL;
        #pragma unroll
        for (int i = 0; i < NI; i++) {
            // logit (log2 domain) = f0*(c0 + c2*f0) + f1*(c1 + c3*f1)
            const u64 t1 = fma2(c2, F0[i], c0);
            const u64 t2 = fma2(c3, F1[i], c1);
            const u64 t3 = mul2(F1[i], t2);
            const u64 lg = fma2(F0[i], t1, t3);
            float llo, lhi; upk2(lg, llo, lhi);
            const u64 e = pk2(ex2a(llo), ex2a(lhi));
            se = add2(se, e);
            n0 = fma2(e, F0[i], n0);
            n1 = fma2(e, F1[i], n1);
        }

        // packed reciprocal with one Newton refinement: r = r*(2 - se*r)
        float slo, shi; upk2(se, slo, shi);
        u64 r = pk2(rcpa(slo), rcpa(shi));
        const u64 sr = mul2(se, r);
        r = mul2(r, fma2(sr, NEG1, TWO));

        const u64 s0 = mul2(n0, r);
        const u64 s1 = mul2(n1, r);

        const int rr = rj >> 1;
        acc[rr * 2 + 0] = fma2(s_M[rj][0], s0, fma2(s_M[rj][1], s1, acc[rr * 2 + 0]));
        acc[rr * 2 + 1] = fma2(s_M[rj][2], s0, fma2(s_M[rj][3], s1, acc[rr * 2 + 1]));
    }

    // ---- unpack and store both elements (48B each, float4-aligned) ----
    float alo[NR * NL], ahi[NR * NL];
    #pragma unroll
    for (int k = 0; k < NR * NL; k++) upk2(acc[k], alo[k], ahi[k]);

    float4* o1 = reinterpret_cast<float4*>(out + (size_t)t * (NR * NL));
    float4* o2 = reinterpret_cast<float4*>(out + (size_t)(t + half) * (NR * NL));
    o1[0] = make_float4(alo[0], alo[1], alo[2],  alo[3]);
    o1[1] = make_float4(alo[4], alo[5], alo[6],  alo[7]);
    o1[2] = make_float4(alo[8], alo[9], alo[10], alo[11]);
    o2[0] = make_float4(ahi[0], ahi[1], ahi[2],  ahi[3]);
    o2[1] = make_float4(ahi[4], ahi[5], ahi[6],  ahi[7]);
    o2[2] = make_float4(ahi[8], ahi[9], ahi[10], ahi[11]);
}

extern "C" void kernel_launch(void* const* d_in, const int* in_sizes, int n_in,
                              void* d_out, int out_size) {
    const float* feat      = (const float*)d_in[0];
    const float* templates = (const float*)d_in[1];
    const float* gammas    = (const float*)d_in[2];
    const float* body_W    = (const float*)d_in[3];
    const float* body_b    = (const float*)d_in[4];
    const float* head_W    = (const float*)d_in[5];
    const float* head_b    = (const float*)d_in[6];
    float* out = (float*)d_out;

    const int B = in_sizes[0] / (NI * NL);
    const int half = B >> 1;
    const int threads = 256;
    const int blocks = (half + threads - 1) / threads;
    abstraction_layer_kernel<<<blocks, threads>>>(
        feat, templates, gammas, body_W, body_b, head_W, head_b, out, B);
}

// round 3
// speedup vs baseline: 1.3692x; 1.1846x over previous
#include <cuda_runtime.h>

// AbstractionLayer: B=524288, I=12, R=6, J=2, L=2, V=4
// Packed f32x2, 2 elements/thread (t, t+B/2). Features parked in
// conflict-free shared memory (per-thread private slots, LDS.128 returns
// them pre-packed -> frees 48 regs, no pack MOVs). Outer rule loop kept
// dynamic so only 2 packed accumulators live. Softmax max-pass removed
// (logits bounded in [-1.2,2.4]); log2e folded into coefs (raw ex2);
// head*body pre-fused; rcp.approx without Newton (tolerance 1e-3).

#define NI 12
#define NR 6
#define NJ 2
#define NL 2
#define NV 4
#define NRJ 12
#define NT 128
#define LOG2E 1.4426950408889634f

typedef unsigned long long u64;

__device__ __forceinline__ u64 pk2(float lo, float hi) {
    u64 r; asm("mov.b64 %0, {%1,%2};" : "=l"(r) : "f"(lo), "f"(hi)); return r;
}
__device__ __forceinline__ void upk2(u64 v, float& lo, float& hi) {
    asm("mov.b64 {%0,%1}, %2;" : "=f"(lo), "=f"(hi) : "l"(v));
}
__device__ __forceinline__ u64 fma2(u64 a, u64 b, u64 c) {
    u64 d; asm("fma.rn.f32x2 %0, %1, %2, %3;" : "=l"(d) : "l"(a), "l"(b), "l"(c)); return d;
}
__device__ __forceinline__ u64 mul2(u64 a, u64 b) {
    u64 d; asm("mul.rn.f32x2 %0, %1, %2;" : "=l"(d) : "l"(a), "l"(b)); return d;
}
__device__ __forceinline__ u64 add2(u64 a, u64 b) {
    u64 d; asm("add.rn.f32x2 %0, %1, %2;" : "=l"(d) : "l"(a), "l"(b)); return d;
}
__device__ __forceinline__ float ex2a(float x) {
    float r; asm("ex2.approx.ftz.f32 %0, %1;" : "=f"(r) : "f"(x)); return r;
}
__device__ __forceinline__ float rcpa(float x) {
    float r; asm("rcp.approx.ftz.f32 %0, %1;" : "=f"(r) : "f"(x)); return r;
}

__global__ __launch_bounds__(NT, 6)
void abstraction_layer_kernel(
    const float* __restrict__ feat,       // [B, I, L]
    const float* __restrict__ templates,  // [R, J, L]
    const float* __restrict__ gammas,     // [R, J, L]
    const float* __restrict__ body_W,     // [R, J, V, L]
    const float* __restrict__ body_b,     // [R, J, V]
    const float* __restrict__ head_W,     // [R, L, V]
    const float* __restrict__ head_b,     // [R, L]
    float* __restrict__ out,              // [B, R, L]
    int B)
{
    __shared__ u64 s_coef[NRJ][4];       // log2e-scaled logit coefs, lane-dup
    __shared__ u64 s_M[NRJ][4];          // fused head*body, lane-dup
    __shared__ u64 s_c[NR * NL];         // fused bias, lane-dup
    __shared__ ulonglong2 sF[NI][NT];    // packed features: (F0,F1) per (i,thread)

    const int tid = threadIdx.x;

    // ---- one-time parameter fusion (disjoint thread ranges) ----
    if (tid < NRJ) {
        const int r = tid >> 1, j = tid & 1;
        #pragma unroll
        for (int l = 0; l < NL; l++) {
            float g = gammas[(r * NJ + j) * NL + l];
            g = fminf(fmaxf(g, 0.0f), 1.0f);
            const float w = 1.0f - g;
            const float t = templates[(r * NJ + j) * NL + l];
            const float clin  = 2.0f * w * t * LOG2E;
            const float cquad = -w * LOG2E;
            s_coef[tid][l]     = pk2(clin, clin);
            s_coef[tid][2 + l] = pk2(cquad, cquad);
        }
    } else if (tid >= 16 && tid < 16 + 48) {
        const int idx = tid - 16;
        const int l2 = idx & 1, j = (idx >> 1) & 1, l = (idx >> 2) & 1, r = idx >> 3;
        float acc = 0.0f;
        #pragma unroll
        for (int v = 0; v < NV; v++)
            acc += head_W[(r * NL + l) * NV + v] *
                   body_W[((r * NJ + j) * NV + v) * NL + l2];
        s_M[r * NJ + j][l * 2 + l2] = pk2(acc, acc);
    } else if (tid >= 64 && tid < 64 + NR * NL) {
        const int idx = tid - 64;
        const int r = idx >> 1, l = idx & 1;
        float acc = head_b[r * NL + l];
        #pragma unroll
        for (int v = 0; v < NV; v++)
            acc += head_W[(r * NL + l) * NV + v] *
                   (body_b[(r * NJ + 0) * NV + v] + body_b[(r * NJ + 1) * NV + v]);
        s_c[idx] = pk2(acc, acc);
    }
    __syncthreads();

    const int half = B >> 1;
    const int t = blockIdx.x * blockDim.x + tid;
    if (t >= half) return;

    // ---- load features of elements (t, t+half), pack into private smem ----
    {
        const float4* fa = reinterpret_cast<const float4*>(feat + (size_t)t * (NI * NL));
        const float4* fb = reinterpret_cast<const float4*>(feat + (size_t)(t + half) * (NI * NL));
        #pragma unroll
        for (int k = 0; k < 6; k++) {
            const float4 a = fa[k];
            const float4 b = fb[k];
            sF[2 * k][tid]     = make_ulonglong2(pk2(a.x, b.x), pk2(a.y, b.y));
            sF[2 * k + 1][tid] = make_ulonglong2(pk2(a.z, b.z), pk2(a.w, b.w));
        }
    }

    float* o1 = out + (size_t)t * (NR * NL);
    float* o2 = out + (size_t)(t + half) * (NR * NL);

    #pragma unroll 1
    for (int r = 0; r < NR; r++) {
        u64 a0 = s_c[2 * r + 0];
        u64 a1 = s_c[2 * r + 1];

        #pragma unroll
        for (int j = 0; j < NJ; j++) {
            const int rj = 2 * r + j;
            const u64 c0 = s_coef[rj][0], c1 = s_coef[rj][1];
            const u64 c2 = s_coef[rj][2], c3 = s_coef[rj][3];

            u64 se = 0ULL, n0 = 0ULL, n1 = 0ULL;
            #pragma unroll
            for (int i = 0; i < NI; i++) {
                const ulonglong2 F = sF[i][tid];     // LDS.128, pre-packed
                const u64 t1 = fma2(c2, F.x, c0);    // f0*(c0+c2*f0)+f1*(c1+c3*f1)
                const u64 t2 = fma2(c3, F.y, c1);
                const u64 t3 = mul2(F.y, t2);
                const u64 lg = fma2(F.x, t1, t3);
                float llo, lhi; upk2(lg, llo, lhi);
                const u64 e = pk2(ex2a(llo), ex2a(lhi));
                se = add2(se, e);
                n0 = fma2(e, F.x, n0);
                n1 = fma2(e, F.y, n1);
            }

            float slo, shi; upk2(se, slo, shi);
            const u64 rinv = pk2(rcpa(slo), rcpa(shi));
            const u64 s0 = mul2(n0, rinv);
            const u64 s1 = mul2(n1, rinv);

            a0 = fma2(s_M[rj][0], s0, fma2(s_M[rj][1], s1, a0));
            a1 = fma2(s_M[rj][2], s0, fma2(s_M[rj][3], s1, a1));
        }

        float x0, x1, y0, y1;
        upk2(a0, x0, x1);
        upk2(a1, y0, y1);
        *reinterpret_cast<float2*>(o1 + r * 2) = make_float2(x0, y0);
        *reinterpret_cast<float2*>(o2 + r * 2) = make_float2(x1, y1);
    }
}

extern "C" void kernel_launch(void* const* d_in, const int* in_sizes, int n_in,
                              void* d_out, int out_size) {
    const float* feat      = (const float*)d_in[0];
    const float* templates = (const float*)d_in[1];
    const float* gammas    = (const float*)d_in[2];
    const float* body_W    = (const float*)d_in[3];
    const float* body_b    = (const float*)d_in[4];
    const float* head_W    = (const float*)d_in[5];
    const float* head_b    = (const float*)d_in[6];
    float* out = (float*)d_out;

    const int B = in_sizes[0] / (NI * NL);
    const int half = B >> 1;
    const int blocks = (half + NT - 1) / NT;
    abstraction_layer_kernel<<<blocks, NT>>>(
        feat, templates, gammas, body_W, body_b, head_W, head_b, out, B);
}